// round 6
// baseline (speedup 1.0000x reference)
#include <cuda_runtime.h>
#include <math.h>
#include <stddef.h>
#include <stdint.h>

// Problem constants
#define D_MODEL 768
#define NHEAD   12
#define HDIM    64
#define BATCH   8
#define TLEN    1024
#define SLEN    257
#define MROWS   (BATCH * TLEN)   // 8192
#define EROWS   (BATCH * SLEN)   // 2056

// ---------------- scratch (static device globals; no allocation) ------------
__device__ float g_big[(size_t)MROWS * 3072];
__device__ float g_h  [(size_t)MROWS * D_MODEL];
__device__ float g_o  [(size_t)MROWS * D_MODEL];
__device__ float g_x  [(size_t)MROWS * D_MODEL];
__device__ float g_q2 [(size_t)MROWS * D_MODEL];
__device__ float g_ekv[(size_t)EROWS * 1536];

// ---------------------------- LayerNorm (d = 768) ---------------------------
__global__ __launch_bounds__(256) void ln_kernel(
    const float* __restrict__ x, const float* __restrict__ g,
    const float* __restrict__ b, float* __restrict__ y)
{
    const int row = blockIdx.x;
    const int tid = threadIdx.x;
    const float* xr = x + (size_t)row * D_MODEL;

    float v0 = xr[tid], v1 = xr[tid + 256], v2 = xr[tid + 512];
    float s  = v0 + v1 + v2;
    float sq = v0 * v0 + v1 * v1 + v2 * v2;

    #pragma unroll
    for (int off = 16; off >= 1; off >>= 1) {
        s  += __shfl_xor_sync(0xffffffffu, s,  off);
        sq += __shfl_xor_sync(0xffffffffu, sq, off);
    }
    __shared__ float ss[8], ssq[8];
    int w = tid >> 5, l = tid & 31;
    if (l == 0) { ss[w] = s; ssq[w] = sq; }
    __syncthreads();
    float st = 0.f, sqt = 0.f;
    #pragma unroll
    for (int i = 0; i < 8; i++) { st += ss[i]; sqt += ssq[i]; }

    const float mean = st * (1.f / 768.f);
    const float var  = sqt * (1.f / 768.f) - mean * mean;
    const float rstd = rsqrtf(var + 1e-5f);

    float* yr = y + (size_t)row * D_MODEL;
    yr[tid]       = (v0 - mean) * rstd * g[tid]       + b[tid];
    yr[tid + 256] = (v1 - mean) * rstd * g[tid + 256] + b[tid + 256];
    yr[tid + 512] = (v2 - mean) * rstd * g[tid + 512] + b[tid + 512];
}

// ------------------------------ shared helpers -------------------------------
__device__ __forceinline__ float gelu_tanh(float v) {
    return 0.5f * v * (1.f + tanhf(0.7978845608028654f * (v + 0.044715f * v * v * v)));
}

__device__ __forceinline__ void mma_tf32(float c[4],
    uint32_t a0, uint32_t a1, uint32_t a2, uint32_t a3,
    uint32_t b0, uint32_t b1)
{
    asm volatile(
        "mma.sync.aligned.m16n8k8.row.col.f32.tf32.tf32.f32 "
        "{%0,%1,%2,%3}, {%4,%5,%6,%7}, {%8,%9}, {%0,%1,%2,%3};"
        : "+f"(c[0]), "+f"(c[1]), "+f"(c[2]), "+f"(c[3])
        : "r"(a0), "r"(a1), "r"(a2), "r"(a3), "r"(b0), "r"(b1));
}

__device__ __forceinline__ void cp16(uint32_t dst_smem, const float* src) {
    asm volatile("cp.async.cg.shared.global [%0], [%1], 16;"
                 :: "r"(dst_smem), "l"(src));
}

// ------------------------------ tf32 GEMM -----------------------------------
// C[M,N] = A[M,K] @ W[K,N] + bias (+resid | GELU). m16n8k8 tf32.
// CTA 128x128x32, 256 threads (8 warps, 2m x 4n), warp tile 64x32.
// A: LDG reg-prefetch -> fragment-order SMEM [2 buf][8 mb][4 s][32 lane][4]
//    (mainloop A-frag = one LDS.128 per m16 block).
// B: 4-stage cp.async, k-major [32][136] (bank 8tg+g, conflict-free).
#define BLDB 136
#define AFRAG 4096                      // floats per A buffer (128 x 32)
#define BSTG  (32 * BLDB)               // 4352 floats per B stage
#define GEMM_SMEM_BYTES ((2 * AFRAG + 4 * BSTG) * 4)   // 102400 B

__device__ __forceinline__ void store_afrags(
    float* dst, const float4 areg[4], int mb, int g, int gh, int half)
{
    #pragma unroll
    for (int i = 0; i < 4; i++) {
        const int s  = 2 * half + (i >> 1);
        const int kh = i & 1;
        float* base = dst + ((mb * 4 + s) * 32 + g * 4) * 4 + gh + 2 * kh;
        base[0]  = areg[i].x;
        base[4]  = areg[i].y;
        base[8]  = areg[i].z;
        base[12] = areg[i].w;
    }
}

__global__ __launch_bounds__(256, 2) void gemm_tf32_kernel(
    const float* __restrict__ A, int lda,
    const float* __restrict__ W, int ldw,
    const float* __restrict__ bias,
    const float* __restrict__ resid,
    float* __restrict__ C, int ldc,
    int M, int N, int K, int mode)   // mode: 0 plain, 1 +resid, 2 gelu
{
    extern __shared__ float sm[];
    float* Afrag = sm;                   // [2][AFRAG]
    float* Bsm   = sm + 2 * AFRAG;       // [4][32][136]

    const int tid = threadIdx.x, lane = tid & 31, wid = tid >> 5;
    const int wm = wid & 1, wn = wid >> 1;   // warps: 2 (m) x 4 (n)
    const int g = lane >> 2, tg = lane & 3;
    const int bm = blockIdx.y * 128, bn = blockIdx.x * 128;

    // A: thread loads 16 floats of row r at k-offset half*16
    const int r = tid >> 1, half = tid & 1;
    int ar = bm + r; if (ar >= M) ar = M - 1;
    const float* aptr = A + (size_t)ar * lda + half * 16;
    const int mbA = r >> 4, ghA = (r >> 3) & 1, gA = r & 7;

    // B: thread loads 16 floats: row tid>>3, col (tid&7)*16
    const int brow = tid >> 3, bcol = (tid & 7) * 16;
    const float* bptr = W + (size_t)brow * ldw + bn + bcol;
    const uint32_t smem0 = (uint32_t)__cvta_generic_to_shared(sm);
    const uint32_t dB0 = smem0 + (2 * AFRAG + brow * BLDB + bcol) * 4;
    const uint32_t stB = BSTG * 4;

    float acc[4][4][4];
    #pragma unroll
    for (int mt = 0; mt < 4; mt++)
        #pragma unroll
        for (int nt = 0; nt < 4; nt++)
            #pragma unroll
            for (int e = 0; e < 4; e++) acc[mt][nt][e] = 0.f;

    const int nk = K >> 5;
    float4 areg[4];

    // ---- prologue: A tile 0 into Afrag[0]; B stages 0..2 committed ----
    {
        const float* p = aptr;
        areg[0] = *(const float4*)(p);
        areg[1] = *(const float4*)(p + 4);
        areg[2] = *(const float4*)(p + 8);
        areg[3] = *(const float4*)(p + 12);
        store_afrags(Afrag, areg, mbA, gA, ghA, half);
    }
    #pragma unroll
    for (int st = 0; st < 3; st++) {
        if (st < nk) {
            const float* pb = bptr + (size_t)st * 32 * ldw;
            const uint32_t sB = dB0 + st * stB;
            #pragma unroll
            for (int i = 0; i < 4; i++) cp16(sB + i * 16, pb + 4 * i);
        }
        asm volatile("cp.async.commit_group;");
    }

    for (int kt = 0; kt < nk; kt++) {
        // LDG A for next tile (latency hidden behind this tile's MMAs)
        if (kt + 1 < nk) {
            const float* p = aptr + (size_t)(kt + 1) * 32;
            areg[0] = *(const float4*)(p);
            areg[1] = *(const float4*)(p + 4);
            areg[2] = *(const float4*)(p + 8);
            areg[3] = *(const float4*)(p + 12);
        }

        asm volatile("cp.async.wait_group 2;");   // B stage kt resident
        __syncthreads();

        // issue B stage kt+3 (buffer (kt+3)&3 = (kt-1)&3; readers done)
        if (kt + 3 < nk) {
            const float* pb = bptr + (size_t)(kt + 3) * 32 * ldw;
            const uint32_t sB = dB0 + ((kt + 3) & 3) * stB;
            #pragma unroll
            for (int i = 0; i < 4; i++) cp16(sB + i * 16, pb + 4 * i);
        }
        asm volatile("cp.async.commit_group;");

        const float*    Af = Afrag + (kt & 1) * AFRAG;
        const uint32_t* Bu = (const uint32_t*)(Bsm + (kt & 3) * BSTG);

        #pragma unroll
        for (int s = 0; s < 4; s++) {
            float4 afv[4];
            #pragma unroll
            for (int mt = 0; mt < 4; mt++) {
                const int mb = wm * 4 + mt;
                afv[mt] = *(const float4*)&Af[((mb * 4 + s) * 32 + lane) * 4];
            }
            uint32_t bf[4][2];
            #pragma unroll
            for (int nt = 0; nt < 4; nt++) {
                const int n0 = wn * 32 + nt * 8 + g;
                bf[nt][0] = Bu[(8 * s + tg)     * BLDB + n0];
                bf[nt][1] = Bu[(8 * s + tg + 4) * BLDB + n0];
            }
            #pragma unroll
            for (int mt = 0; mt < 4; mt++)
                #pragma unroll
                for (int nt = 0; nt < 4; nt++)
                    mma_tf32(acc[mt][nt],
                             __float_as_uint(afv[mt].x), __float_as_uint(afv[mt].y),
                             __float_as_uint(afv[mt].z), __float_as_uint(afv[mt].w),
                             bf[nt][0], bf[nt][1]);
        }

        // STS A tile kt+1 into Afrag[(kt+1)&1] (readers finished pre-barrier)
        if (kt + 1 < nk)
            store_afrags(Afrag + ((kt + 1) & 1) * AFRAG, areg, mbA, gA, ghA, half);
    }

    // ---- epilogue ----
    #pragma unroll
    for (int mt = 0; mt < 4; mt++) {
        const int r0 = bm + wm * 64 + mt * 16 + g;
        #pragma unroll
        for (int h2 = 0; h2 < 2; h2++) {
            const int row = r0 + 8 * h2;
            if (row >= M) continue;
            #pragma unroll
            for (int nt = 0; nt < 4; nt++) {
                const int col = bn + wn * 32 + nt * 8 + 2 * tg;
                float2 o = make_float2(acc[mt][nt][2 * h2], acc[mt][nt][2 * h2 + 1]);
                float2 bv = *(const float2*)&bias[col];
                o.x += bv.x; o.y += bv.y;
                if (mode == 1) {
                    float2 rv = *(const float2*)&resid[(size_t)row * ldc + col];
                    o.x += rv.x; o.y += rv.y;
                } else if (mode == 2) {
                    o.x = gelu_tanh(o.x); o.y = gelu_tanh(o.y);
                }
                *(float2*)&C[(size_t)row * ldc + col] = o;
            }
        }
    }
}

// ------------------- tensor-core flash attention (tf32) ----------------------
// CTA: 128 q-rows x (64-key tiles). 256 threads = 8 warps; warp w owns rows
// [16w,16w+16). S = Q K^T and O += P V both m16n8k8 tf32. P staged via SMEM.
#define QLD 68
#define KLD 68
#define VLD 72
#define PLD 68
#define ATTN_SMEM_FLOATS (128 * QLD + 64 * KLD + 64 * VLD + 128 * PLD)
#define ATTN_SMEM_BYTES (ATTN_SMEM_FLOATS * 4)   // 105472

__global__ __launch_bounds__(256, 2) void attn_tc_kernel(
    const float* __restrict__ Qp, int q_rs,
    const float* __restrict__ Kp, int k_rs,
    const float* __restrict__ Vp, int v_rs,
    float* __restrict__ Op, int o_rs,
    int Tq, int Tk, int causal)
{
    extern __shared__ float sm[];
    float* Qs = sm;                       // [128][68]
    float* Ks = Qs + 128 * QLD;           // [64][68]
    float* Vs = Ks + 64 * KLD;            // [64][72]
    float* Ps = Vs + 64 * VLD;            // [128][68]

    const int tid = threadIdx.x, lane = tid & 31, wid = tid >> 5;
    const int g = lane >> 2, tg = lane & 3;
    const int b = blockIdx.z, h = blockIdx.y;
    const int q0 = blockIdx.x * 128;
    const int rw = wid * 16;

    const float* qbase = Qp + (size_t)b * Tq * q_rs + h * HDIM;
    const float* kbase = Kp + (size_t)b * Tk * k_rs + h * HDIM;
    const float* vbase = Vp + (size_t)b * Tk * v_rs + h * HDIM;

    {
        const int r = tid >> 1, c0 = (tid & 1) * 32;
        const float* src = qbase + (size_t)(q0 + r) * q_rs + c0;
        uint32_t dst = (uint32_t)__cvta_generic_to_shared(Qs + r * QLD + c0);
        #pragma unroll
        for (int i = 0; i < 8; i++) cp16(dst + i * 16, src + 4 * i);
        asm volatile("cp.async.commit_group;");
    }

    float mrun[2] = {-1e30f, -1e30f}, lrun[2] = {0.f, 0.f};
    float o[8][4];
    #pragma unroll
    for (int nf = 0; nf < 8; nf++)
        #pragma unroll
        for (int e = 0; e < 4; e++) o[nf][e] = 0.f;

    const int ntiles = causal ? 2 * (blockIdx.x + 1) : ((Tk + 63) >> 6);
    const int kv_r = tid >> 2, kv_c = (tid & 3) * 16;

    for (int kt = 0; kt < ntiles; kt++) {
        const int k0 = kt * 64;
        __syncthreads();
        {
            int sr = k0 + kv_r; if (sr >= Tk) sr = Tk - 1;
            const float* ks = kbase + (size_t)sr * k_rs + kv_c;
            const float* vs = vbase + (size_t)sr * v_rs + kv_c;
            uint32_t dk = (uint32_t)__cvta_generic_to_shared(Ks + kv_r * KLD + kv_c);
            uint32_t dv = (uint32_t)__cvta_generic_to_shared(Vs + kv_r * VLD + kv_c);
            #pragma unroll
            for (int i = 0; i < 4; i++) cp16(dk + i * 16, ks + 4 * i);
            #pragma unroll
            for (int i = 0; i < 4; i++) cp16(dv + i * 16, vs + 4 * i);
            asm volatile("cp.async.commit_group;");
        }
        asm volatile("cp.async.wait_group 0;");
        __syncthreads();

        float sc[8][4];
        #pragma unroll
        for (int nf = 0; nf < 8; nf++)
            #pragma unroll
            for (int e = 0; e < 4; e++) sc[nf][e] = 0.f;

        const uint32_t* Qu = (const uint32_t*)Qs;
        const uint32_t* Ku = (const uint32_t*)Ks;
        #pragma unroll
        for (int ks = 0; ks < 8; ks++) {
            const int k = 8 * ks;
            uint32_t a0 = Qu[(rw + g)     * QLD + k + tg];
            uint32_t a1 = Qu[(rw + g + 8) * QLD + k + tg];
            uint32_t a2 = Qu[(rw + g)     * QLD + k + tg + 4];
            uint32_t a3 = Qu[(rw + g + 8) * QLD + k + tg + 4];
            #pragma unroll
            for (int nf = 0; nf < 8; nf++) {
                uint32_t b0 = Ku[(8 * nf + g) * KLD + k + tg];
                uint32_t b1 = Ku[(8 * nf + g) * KLD + k + tg + 4];
                mma_tf32(sc[nf], a0, a1, a2, a3, b0, b1);
            }
        }

        const int qi0 = q0 + rw + g, qi1 = qi0 + 8;
        const int cmax0 = causal ? min(qi0, Tk - 1) : (Tk - 1);
        const int cmax1 = causal ? min(qi1, Tk - 1) : (Tk - 1);
        float m0 = -1e30f, m1 = -1e30f;
        #pragma unroll
        for (int nf = 0; nf < 8; nf++) {
            const int c0i = k0 + 8 * nf + 2 * tg;
            const int c1i = c0i + 1;
            sc[nf][0] = (c0i <= cmax0) ? sc[nf][0] * 0.125f : -1e30f;
            sc[nf][1] = (c1i <= cmax0) ? sc[nf][1] * 0.125f : -1e30f;
            sc[nf][2] = (c0i <= cmax1) ? sc[nf][2] * 0.125f : -1e30f;
            sc[nf][3] = (c1i <= cmax1) ? sc[nf][3] * 0.125f : -1e30f;
            m0 = fmaxf(m0, fmaxf(sc[nf][0], sc[nf][1]));
            m1 = fmaxf(m1, fmaxf(sc[nf][2], sc[nf][3]));
        }
        #pragma unroll
        for (int off = 1; off < 4; off <<= 1) {
            m0 = fmaxf(m0, __shfl_xor_sync(0xffffffffu, m0, off));
            m1 = fmaxf(m1, __shfl_xor_sync(0xffffffffu, m1, off));
        }
        const float mn0 = fmaxf(mrun[0], m0), mn1 = fmaxf(mrun[1], m1);
        const float corr0 = __expf(mrun[0] - mn0), corr1 = __expf(mrun[1] - mn1);
        mrun[0] = mn0; mrun[1] = mn1;

        float s0 = 0.f, s1 = 0.f;
        #pragma unroll
        for (int nf = 0; nf < 8; nf++) {
            float p00 = __expf(sc[nf][0] - mn0);
            float p01 = __expf(sc[nf][1] - mn0);
            float p10 = __expf(sc[nf][2] - mn1);
            float p11 = __expf(sc[nf][3] - mn1);
            s0 += p00 + p01; s1 += p10 + p11;
            *(float2*)&Ps[(rw + g)     * PLD + 8 * nf + 2 * tg] = make_float2(p00, p01);
            *(float2*)&Ps[(rw + g + 8) * PLD + 8 * nf + 2 * tg] = make_float2(p10, p11);
            o[nf][0] *= corr0; o[nf][1] *= corr0;
            o[nf][2] *= corr1; o[nf][3] *= corr1;
        }
        #pragma unroll
        for (int off = 1; off < 4; off <<= 1) {
            s0 += __shfl_xor_sync(0xffffffffu, s0, off);
            s1 += __shfl_xor_sync(0xffffffffu, s1, off);
        }
        lrun[0] = lrun[0] * corr0 + s0;
        lrun[1] = lrun[1] * corr1 + s1;
        __syncwarp();

        const uint32_t* Pu = (const uint32_t*)Ps;
        const uint32_t* Vu = (const uint32_t*)Vs;
        #pragma unroll
        for (int ks = 0; ks < 8; ks++) {
            const int k = 8 * ks;
            uint32_t a0 = Pu[(rw + g)     * PLD + k + tg];
            uint32_t a1 = Pu[(rw + g + 8) * PLD + k + tg];
            uint32_t a2 = Pu[(rw + g)     * PLD + k + tg + 4];
            uint32_t a3 = Pu[(rw + g + 8) * PLD + k + tg + 4];
            #pragma unroll
            for (int nf = 0; nf < 8; nf++) {
                uint32_t b0 = Vu[(k + tg)     * VLD + 8 * nf + g];
                uint32_t b1 = Vu[(k + tg + 4) * VLD + 8 * nf + g];
                mma_tf32(o[nf], a0, a1, a2, a3, b0, b1);
            }
        }
    }

    const float inv0 = 1.f / lrun[0], inv1 = 1.f / lrun[1];
    const int t0 = q0 + rw + g, t1 = t0 + 8;
    float* out0 = Op + ((size_t)b * Tq + t0) * o_rs + h * HDIM;
    float* out1 = Op + ((size_t)b * Tq + t1) * o_rs + h * HDIM;
    #pragma unroll
    for (int nf = 0; nf < 8; nf++) {
        const int col = 8 * nf + 2 * tg;
        *(float2*)&out0[col] = make_float2(o[nf][0] * inv0, o[nf][1] * inv0);
        *(float2*)&out1[col] = make_float2(o[nf][2] * inv1, o[nf][3] * inv1);
    }
}

// ------------------------------- launch --------------------------------------
extern "C" void kernel_launch(void* const* d_in, const int* in_sizes, int n_in,
                              void* d_out, int out_size)
{
    const float* x            = (const float*)d_in[0];
    const float* encoder_x    = (const float*)d_in[1];
    const float* ln1_g        = (const float*)d_in[2];
    const float* ln1_b        = (const float*)d_in[3];
    const float* ln2_g        = (const float*)d_in[4];
    const float* ln2_b        = (const float*)d_in[5];
    const float* ln3_g        = (const float*)d_in[6];
    const float* ln3_b        = (const float*)d_in[7];
    const float* attn_w       = (const float*)d_in[8];
    const float* attn_b       = (const float*)d_in[9];
    const float* attn_proj_w  = (const float*)d_in[10];
    const float* attn_proj_b  = (const float*)d_in[11];
    const float* cross_w      = (const float*)d_in[12];
    const float* cross_b      = (const float*)d_in[13];
    const float* cross_proj_w = (const float*)d_in[14];
    const float* cross_proj_b = (const float*)d_in[15];
    const float* fc_w         = (const float*)d_in[16];
    const float* fc_b         = (const float*)d_in[17];
    const float* proj_w       = (const float*)d_in[18];
    const float* proj_b       = (const float*)d_in[19];

    float *big, *hbuf, *obuf, *xbuf, *q2, *ekv;
    cudaGetSymbolAddress((void**)&big,  g_big);
    cudaGetSymbolAddress((void**)&hbuf, g_h);
    cudaGetSymbolAddress((void**)&obuf, g_o);
    cudaGetSymbolAddress((void**)&xbuf, g_x);
    cudaGetSymbolAddress((void**)&q2,   g_q2);
    cudaGetSymbolAddress((void**)&ekv,  g_ekv);

    cudaFuncSetAttribute(attn_tc_kernel,
                         cudaFuncAttributeMaxDynamicSharedMemorySize,
                         ATTN_SMEM_BYTES);
    cudaFuncSetAttribute(gemm_tf32_kernel,
                         cudaFuncAttributeMaxDynamicSharedMemorySize,
                         GEMM_SMEM_BYTES);

    const int M = MROWS;        // 8192
    dim3 blk(256);
    dim3 ga(TLEN / 128, NHEAD, BATCH);   // 8 x 12 x 8

    // 1. h = LN1(x)
    ln_kernel<<<M, blk>>>(x, ln1_g, ln1_b, hbuf);
    // 2. qkv = h @ attn_w + attn_b   (8192 x 2304)
    gemm_tf32_kernel<<<dim3(2304 / 128, M / 128), blk, GEMM_SMEM_BYTES>>>(
        hbuf, 768, attn_w, 2304, attn_b, nullptr, big, 2304, M, 2304, 768, 0);
    // 3. causal self-attention
    attn_tc_kernel<<<ga, blk, ATTN_SMEM_BYTES>>>(
        big, 2304, big + 768, 2304, big + 1536, 2304, obuf, 768, TLEN, TLEN, 1);
    // 4. x1 = x + o @ attn_proj_w + attn_proj_b
    gemm_tf32_kernel<<<dim3(768 / 128, M / 128), blk, GEMM_SMEM_BYTES>>>(
        obuf, 768, attn_proj_w, 768, attn_proj_b, x, xbuf, 768, M, 768, 768, 1);
    // 5. h = LN2(x1)
    ln_kernel<<<M, blk>>>(xbuf, ln2_g, ln2_b, hbuf);
    // 6. q2 = h @ cross_w[:, :768] + cross_b[:768]
    gemm_tf32_kernel<<<dim3(768 / 128, M / 128), blk, GEMM_SMEM_BYTES>>>(
        hbuf, 768, cross_w, 2304, cross_b, nullptr, q2, 768, M, 768, 768, 0);
    // 7. ekv = encoder_x @ cross_w[:, 768:] + cross_b[768:]   (2056 x 1536)
    gemm_tf32_kernel<<<dim3(1536 / 128, (EROWS + 127) / 128), blk, GEMM_SMEM_BYTES>>>(
        encoder_x, 768, cross_w + 768, 2304, cross_b + 768, nullptr,
        ekv, 1536, EROWS, 1536, 768, 0);
    // 8. cross-attention (non-causal, Tk = 257)
    attn_tc_kernel<<<ga, blk, ATTN_SMEM_BYTES>>>(
        q2, 768, ekv, 1536, ekv + 768, 1536, obuf, 768, TLEN, SLEN, 0);
    // 9. x2 = x1 + o2 @ cross_proj_w + cross_proj_b
    gemm_tf32_kernel<<<dim3(768 / 128, M / 128), blk, GEMM_SMEM_BYTES>>>(
        obuf, 768, cross_proj_w, 768, cross_proj_b, xbuf, xbuf, 768, M, 768, 768, 1);
    // 10. h = LN3(x2)
    ln_kernel<<<M, blk>>>(xbuf, ln3_g, ln3_b, hbuf);
    // 11. fc = GELU(h @ fc_w + fc_b)  (8192 x 3072)
    gemm_tf32_kernel<<<dim3(3072 / 128, M / 128), blk, GEMM_SMEM_BYTES>>>(
        hbuf, 768, fc_w, 3072, fc_b, nullptr, big, 3072, M, 3072, 768, 2);
    // 12. out = x2 + fc @ proj_w + proj_b
    gemm_tf32_kernel<<<dim3(768 / 128, M / 128), blk, GEMM_SMEM_BYTES>>>(
        big, 3072, proj_w, 768, proj_b, xbuf, (float*)d_out, 768, M, 768, 3072, 1);
}

// round 7
// speedup vs baseline: 1.2586x; 1.2586x over previous
#include <cuda_runtime.h>
#include <math.h>
#include <stddef.h>
#include <stdint.h>

// Problem constants
#define D_MODEL 768
#define NHEAD   12
#define HDIM    64
#define BATCH   8
#define TLEN    1024
#define SLEN    257
#define MROWS   (BATCH * TLEN)   // 8192
#define EROWS   (BATCH * SLEN)   // 2056

// ---------------- scratch (static device globals; no allocation) ------------
__device__ float g_big[(size_t)MROWS * 3072];
__device__ float g_h  [(size_t)MROWS * D_MODEL];
__device__ float g_o  [(size_t)MROWS * D_MODEL];
__device__ float g_x  [(size_t)MROWS * D_MODEL];
__device__ float g_q2 [(size_t)MROWS * D_MODEL];
__device__ float g_ekv[(size_t)EROWS * 1536];

// ---------------------------- LayerNorm (d = 768) ---------------------------
__global__ __launch_bounds__(256) void ln_kernel(
    const float* __restrict__ x, const float* __restrict__ g,
    const float* __restrict__ b, float* __restrict__ y)
{
    const int row = blockIdx.x;
    const int tid = threadIdx.x;
    const float* xr = x + (size_t)row * D_MODEL;

    float v0 = xr[tid], v1 = xr[tid + 256], v2 = xr[tid + 512];
    float s  = v0 + v1 + v2;
    float sq = v0 * v0 + v1 * v1 + v2 * v2;

    #pragma unroll
    for (int off = 16; off >= 1; off >>= 1) {
        s  += __shfl_xor_sync(0xffffffffu, s,  off);
        sq += __shfl_xor_sync(0xffffffffu, sq, off);
    }
    __shared__ float ss[8], ssq[8];
    int w = tid >> 5, l = tid & 31;
    if (l == 0) { ss[w] = s; ssq[w] = sq; }
    __syncthreads();
    float st = 0.f, sqt = 0.f;
    #pragma unroll
    for (int i = 0; i < 8; i++) { st += ss[i]; sqt += ssq[i]; }

    const float mean = st * (1.f / 768.f);
    const float var  = sqt * (1.f / 768.f) - mean * mean;
    const float rstd = rsqrtf(var + 1e-5f);

    float* yr = y + (size_t)row * D_MODEL;
    yr[tid]       = (v0 - mean) * rstd * g[tid]       + b[tid];
    yr[tid + 256] = (v1 - mean) * rstd * g[tid + 256] + b[tid + 256];
    yr[tid + 512] = (v2 - mean) * rstd * g[tid + 512] + b[tid + 512];
}

// ------------------------------ shared helpers -------------------------------
__device__ __forceinline__ float gelu_tanh(float v) {
    return 0.5f * v * (1.f + tanhf(0.7978845608028654f * (v + 0.044715f * v * v * v)));
}

__device__ __forceinline__ void mma_tf32(float c[4],
    uint32_t a0, uint32_t a1, uint32_t a2, uint32_t a3,
    uint32_t b0, uint32_t b1)
{
    asm volatile(
        "mma.sync.aligned.m16n8k8.row.col.f32.tf32.tf32.f32 "
        "{%0,%1,%2,%3}, {%4,%5,%6,%7}, {%8,%9}, {%0,%1,%2,%3};"
        : "+f"(c[0]), "+f"(c[1]), "+f"(c[2]), "+f"(c[3])
        : "r"(a0), "r"(a1), "r"(a2), "r"(a3), "r"(b0), "r"(b1));
}

__device__ __forceinline__ void cp16(uint32_t dst_smem, const float* src) {
    asm volatile("cp.async.cg.shared.global [%0], [%1], 16;"
                 :: "r"(dst_smem), "l"(src));
}

// ------------------------------ tf32 GEMM (R2 version) -----------------------
// C[M,N] = A[M,K] @ W[K,N] + bias (+resid | GELU). Tensor cores, m16n8k8 tf32.
// CTA tile 128x128x32, 256 threads (8 warps, 2x4), warp tile 64x32.
// SMEM: As[2][32][136] (k-major, transposed), Bs[2][32][136]. Double buffered.
#define SLDA 136
#define GEMM_SMEM_BYTES (2 * 2 * 32 * SLDA * 4)   // 69632 B

__global__ __launch_bounds__(256, 2) void gemm_tf32_kernel(
    const float* __restrict__ A, int lda,
    const float* __restrict__ W, int ldw,
    const float* __restrict__ bias,
    const float* __restrict__ resid,
    float* __restrict__ C, int ldc,
    int M, int N, int K, int mode)   // mode: 0 plain, 1 +resid, 2 gelu
{
    extern __shared__ float sm[];
    float* Asm = sm;                    // [2][32][SLDA]
    float* Bsm = sm + 2 * 32 * SLDA;    // [2][32][SLDA]

    const int tid = threadIdx.x, lane = tid & 31, wid = tid >> 5;
    const int wm = wid & 1, wn = wid >> 1;      // warps: 2 (m) x 4 (n)
    const int g = lane >> 2, tg = lane & 3;
    const int bm = blockIdx.y * 128, bn = blockIdx.x * 128;

    // A gmem: thread loads 16 floats of one row: row tid>>1, k-offset (tid&1)*16
    const int arow = tid >> 1, acol = (tid & 1) * 16;
    int ar = bm + arow; if (ar >= M) ar = M - 1;
    const float* aptr = A + (size_t)ar * lda + acol;

    // B gmem: thread loads 16 floats of one row: row tid>>3, col (tid&7)*16
    const int brow = tid >> 3, bcol = (tid & 7) * 16;
    const float* bptr = W + (size_t)brow * ldw + bn + bcol;

    float c[4][4][4];
    #pragma unroll
    for (int mt = 0; mt < 4; mt++)
        #pragma unroll
        for (int nt = 0; nt < 4; nt++)
            #pragma unroll
            for (int e = 0; e < 4; e++) c[mt][nt][e] = 0.f;

    const int nk = K >> 5;  // K / 32
    float4 areg[4];

    // ---- prologue: tile 0 ----
    {
        const float* p = aptr;
        areg[0] = *(const float4*)(p);
        areg[1] = *(const float4*)(p + 4);
        areg[2] = *(const float4*)(p + 8);
        areg[3] = *(const float4*)(p + 12);
        float* dstB = Bsm + brow * SLDA + bcol;
        uint32_t dB = (uint32_t)__cvta_generic_to_shared(dstB);
        const float* srcB = bptr;
        #pragma unroll
        for (int i = 0; i < 4; i++)
            asm volatile("cp.async.cg.shared.global [%0], [%1], 16;"
                         :: "r"(dB + i * 16), "l"(srcB + i * 4));
        asm volatile("cp.async.commit_group;");
        float* dstA = Asm;
        #pragma unroll
        for (int i = 0; i < 4; i++) {
            dstA[(acol + 4 * i + 0) * SLDA + arow] = areg[i].x;
            dstA[(acol + 4 * i + 1) * SLDA + arow] = areg[i].y;
            dstA[(acol + 4 * i + 2) * SLDA + arow] = areg[i].z;
            dstA[(acol + 4 * i + 3) * SLDA + arow] = areg[i].w;
        }
        asm volatile("cp.async.wait_group 0;");
    }
    __syncthreads();

    for (int kt = 0; kt < nk; kt++) {
        const int db = kt & 1;
        const bool has_next = (kt + 1 < nk);

        if (has_next) {
            const float* p = aptr + (size_t)(kt + 1) * 32;
            areg[0] = *(const float4*)(p);
            areg[1] = *(const float4*)(p + 4);
            areg[2] = *(const float4*)(p + 8);
            areg[3] = *(const float4*)(p + 12);
            float* dstB = Bsm + (db ^ 1) * 32 * SLDA + brow * SLDA + bcol;
            uint32_t dB = (uint32_t)__cvta_generic_to_shared(dstB);
            const float* srcB = bptr + (size_t)(kt + 1) * 32 * ldw;
            #pragma unroll
            for (int i = 0; i < 4; i++)
                asm volatile("cp.async.cg.shared.global [%0], [%1], 16;"
                             :: "r"(dB + i * 16), "l"(srcB + i * 4));
            asm volatile("cp.async.commit_group;");
        }

        const uint32_t* Au = (const uint32_t*)(Asm + db * 32 * SLDA);
        const uint32_t* Bu = (const uint32_t*)(Bsm + db * 32 * SLDA);

        #pragma unroll
        for (int s = 0; s < 4; s++) {
            const int k0 = s * 8;
            uint32_t af[4][4], bf[4][2];
            #pragma unroll
            for (int mt = 0; mt < 4; mt++) {
                const int m0 = wm * 64 + mt * 16 + g;
                af[mt][0] = Au[(k0 + tg) * SLDA + m0];
                af[mt][1] = Au[(k0 + tg) * SLDA + m0 + 8];
                af[mt][2] = Au[(k0 + tg + 4) * SLDA + m0];
                af[mt][3] = Au[(k0 + tg + 4) * SLDA + m0 + 8];
            }
            #pragma unroll
            for (int nt = 0; nt < 4; nt++) {
                const int n0 = wn * 32 + nt * 8 + g;
                bf[nt][0] = Bu[(k0 + tg) * SLDA + n0];
                bf[nt][1] = Bu[(k0 + tg + 4) * SLDA + n0];
            }
            #pragma unroll
            for (int mt = 0; mt < 4; mt++)
                #pragma unroll
                for (int nt = 0; nt < 4; nt++)
                    mma_tf32(c[mt][nt], af[mt][0], af[mt][1], af[mt][2], af[mt][3],
                             bf[nt][0], bf[nt][1]);
        }

        if (has_next) {
            float* dstA = Asm + (db ^ 1) * 32 * SLDA;
            #pragma unroll
            for (int i = 0; i < 4; i++) {
                dstA[(acol + 4 * i + 0) * SLDA + arow] = areg[i].x;
                dstA[(acol + 4 * i + 1) * SLDA + arow] = areg[i].y;
                dstA[(acol + 4 * i + 2) * SLDA + arow] = areg[i].z;
                dstA[(acol + 4 * i + 3) * SLDA + arow] = areg[i].w;
            }
            asm volatile("cp.async.wait_group 0;");
            __syncthreads();
        }
    }

    // ---- epilogue ----
    #pragma unroll
    for (int mt = 0; mt < 4; mt++) {
        const int r0 = bm + wm * 64 + mt * 16 + g;
        #pragma unroll
        for (int h2 = 0; h2 < 2; h2++) {
            const int row = r0 + 8 * h2;
            if (row >= M) continue;
            #pragma unroll
            for (int nt = 0; nt < 4; nt++) {
                const int col = bn + wn * 32 + nt * 8 + 2 * tg;
                float2 o = make_float2(c[mt][nt][2 * h2], c[mt][nt][2 * h2 + 1]);
                float2 bv = *(const float2*)&bias[col];
                o.x += bv.x; o.y += bv.y;
                if (mode == 1) {
                    float2 rv = *(const float2*)&resid[(size_t)row * ldc + col];
                    o.x += rv.x; o.y += rv.y;
                } else if (mode == 2) {
                    o.x = gelu_tanh(o.x); o.y = gelu_tanh(o.y);
                }
                *(float2*)&C[(size_t)row * ldc + col] = o;
            }
        }
    }
}

// ------------------- tensor-core flash attention (tf32) ----------------------
// CTA: 128 q-rows x (64-key tiles). 256 threads = 8 warps; warp w owns rows
// [16w,16w+16). S = Q K^T and O += P V both m16n8k8 tf32. P staged via SMEM.
#define QLD 68
#define KLD 68
#define VLD 72
#define PLD 68
#define ATTN_SMEM_FLOATS (128 * QLD + 64 * KLD + 64 * VLD + 128 * PLD)
#define ATTN_SMEM_BYTES (ATTN_SMEM_FLOATS * 4)   // 105472

__global__ __launch_bounds__(256, 2) void attn_tc_kernel(
    const float* __restrict__ Qp, int q_rs,
    const float* __restrict__ Kp, int k_rs,
    const float* __restrict__ Vp, int v_rs,
    float* __restrict__ Op, int o_rs,
    int Tq, int Tk, int causal)
{
    extern __shared__ float sm[];
    float* Qs = sm;                       // [128][68]
    float* Ks = Qs + 128 * QLD;           // [64][68]
    float* Vs = Ks + 64 * KLD;            // [64][72]
    float* Ps = Vs + 64 * VLD;            // [128][68]

    const int tid = threadIdx.x, lane = tid & 31, wid = tid >> 5;
    const int g = lane >> 2, tg = lane & 3;
    const int b = blockIdx.z, h = blockIdx.y;
    const int q0 = blockIdx.x * 128;
    const int rw = wid * 16;

    const float* qbase = Qp + (size_t)b * Tq * q_rs + h * HDIM;
    const float* kbase = Kp + (size_t)b * Tk * k_rs + h * HDIM;
    const float* vbase = Vp + (size_t)b * Tk * v_rs + h * HDIM;

    {
        const int r = tid >> 1, c0 = (tid & 1) * 32;
        const float* src = qbase + (size_t)(q0 + r) * q_rs + c0;
        uint32_t dst = (uint32_t)__cvta_generic_to_shared(Qs + r * QLD + c0);
        #pragma unroll
        for (int i = 0; i < 8; i++) cp16(dst + i * 16, src + 4 * i);
        asm volatile("cp.async.commit_group;");
    }

    float mrun[2] = {-1e30f, -1e30f}, lrun[2] = {0.f, 0.f};
    float o[8][4];
    #pragma unroll
    for (int nf = 0; nf < 8; nf++)
        #pragma unroll
        for (int e = 0; e < 4; e++) o[nf][e] = 0.f;

    const int ntiles = causal ? 2 * (blockIdx.x + 1) : ((Tk + 63) >> 6);
    const int kv_r = tid >> 2, kv_c = (tid & 3) * 16;

    for (int kt = 0; kt < ntiles; kt++) {
        const int k0 = kt * 64;
        __syncthreads();
        {
            int sr = k0 + kv_r; if (sr >= Tk) sr = Tk - 1;
            const float* ks = kbase + (size_t)sr * k_rs + kv_c;
            const float* vs = vbase + (size_t)sr * v_rs + kv_c;
            uint32_t dk = (uint32_t)__cvta_generic_to_shared(Ks + kv_r * KLD + kv_c);
            uint32_t dv = (uint32_t)__cvta_generic_to_shared(Vs + kv_r * VLD + kv_c);
            #pragma unroll
            for (int i = 0; i < 4; i++) cp16(dk + i * 16, ks + 4 * i);
            #pragma unroll
            for (int i = 0; i < 4; i++) cp16(dv + i * 16, vs + 4 * i);
            asm volatile("cp.async.commit_group;");
        }
        asm volatile("cp.async.wait_group 0;");
        __syncthreads();

        float sc[8][4];
        #pragma unroll
        for (int nf = 0; nf < 8; nf++)
            #pragma unroll
            for (int e = 0; e < 4; e++) sc[nf][e] = 0.f;

        const uint32_t* Qu = (const uint32_t*)Qs;
        const uint32_t* Ku = (const uint32_t*)Ks;
        #pragma unroll
        for (int ks = 0; ks < 8; ks++) {
            const int k = 8 * ks;
            uint32_t a0 = Qu[(rw + g)     * QLD + k + tg];
            uint32_t a1 = Qu[(rw + g + 8) * QLD + k + tg];
            uint32_t a2 = Qu[(rw + g)     * QLD + k + tg + 4];
            uint32_t a3 = Qu[(rw + g + 8) * QLD + k + tg + 4];
            #pragma unroll
            for (int nf = 0; nf < 8; nf++) {
                uint32_t b0 = Ku[(8 * nf + g) * KLD + k + tg];
                uint32_t b1 = Ku[(8 * nf + g) * KLD + k + tg + 4];
                mma_tf32(sc[nf], a0, a1, a2, a3, b0, b1);
            }
        }

        const int qi0 = q0 + rw + g, qi1 = qi0 + 8;
        const int cmax0 = causal ? min(qi0, Tk - 1) : (Tk - 1);
        const int cmax1 = causal ? min(qi1, Tk - 1) : (Tk - 1);
        float m0 = -1e30f, m1 = -1e30f;
        #pragma unroll
        for (int nf = 0; nf < 8; nf++) {
            const int c0i = k0 + 8 * nf + 2 * tg;
            const int c1i = c0i + 1;
            sc[nf][0] = (c0i <= cmax0) ? sc[nf][0] * 0.125f : -1e30f;
            sc[nf][1] = (c1i <= cmax0) ? sc[nf][1] * 0.125f : -1e30f;
            sc[nf][2] = (c0i <= cmax1) ? sc[nf][2] * 0.125f : -1e30f;
            sc[nf][3] = (c1i <= cmax1) ? sc[nf][3] * 0.125f : -1e30f;
            m0 = fmaxf(m0, fmaxf(sc[nf][0], sc[nf][1]));
            m1 = fmaxf(m1, fmaxf(sc[nf][2], sc[nf][3]));
        }
        #pragma unroll
        for (int off = 1; off < 4; off <<= 1) {
            m0 = fmaxf(m0, __shfl_xor_sync(0xffffffffu, m0, off));
            m1 = fmaxf(m1, __shfl_xor_sync(0xffffffffu, m1, off));
        }
        const float mn0 = fmaxf(mrun[0], m0), mn1 = fmaxf(mrun[1], m1);
        const float corr0 = __expf(mrun[0] - mn0), corr1 = __expf(mrun[1] - mn1);
        mrun[0] = mn0; mrun[1] = mn1;

        float s0 = 0.f, s1 = 0.f;
        #pragma unroll
        for (int nf = 0; nf < 8; nf++) {
            float p00 = __expf(sc[nf][0] - mn0);
            float p01 = __expf(sc[nf][1] - mn0);
            float p10 = __expf(sc[nf][2] - mn1);
            float p11 = __expf(sc[nf][3] - mn1);
            s0 += p00 + p01; s1 += p10 + p11;
            *(float2*)&Ps[(rw + g)     * PLD + 8 * nf + 2 * tg] = make_float2(p00, p01);
            *(float2*)&Ps[(rw + g + 8) * PLD + 8 * nf + 2 * tg] = make_float2(p10, p11);
            o[nf][0] *= corr0; o[nf][1] *= corr0;
            o[nf][2] *= corr1; o[nf][3] *= corr1;
        }
        #pragma unroll
        for (int off = 1; off < 4; off <<= 1) {
            s0 += __shfl_xor_sync(0xffffffffu, s0, off);
            s1 += __shfl_xor_sync(0xffffffffu, s1, off);
        }
        lrun[0] = lrun[0] * corr0 + s0;
        lrun[1] = lrun[1] * corr1 + s1;
        __syncwarp();

        const uint32_t* Pu = (const uint32_t*)Ps;
        const uint32_t* Vu = (const uint32_t*)Vs;
        #pragma unroll
        for (int ks = 0; ks < 8; ks++) {
            const int k = 8 * ks;
            uint32_t a0 = Pu[(rw + g)     * PLD + k + tg];
            uint32_t a1 = Pu[(rw + g + 8) * PLD + k + tg];
            uint32_t a2 = Pu[(rw + g)     * PLD + k + tg + 4];
            uint32_t a3 = Pu[(rw + g + 8) * PLD + k + tg + 4];
            #pragma unroll
            for (int nf = 0; nf < 8; nf++) {
                uint32_t b0 = Vu[(k + tg)     * VLD + 8 * nf + g];
                uint32_t b1 = Vu[(k + tg + 4) * VLD + 8 * nf + g];
                mma_tf32(o[nf], a0, a1, a2, a3, b0, b1);
            }
        }
    }

    const float inv0 = 1.f / lrun[0], inv1 = 1.f / lrun[1];
    const int t0 = q0 + rw + g, t1 = t0 + 8;
    float* out0 = Op + ((size_t)b * Tq + t0) * o_rs + h * HDIM;
    float* out1 = Op + ((size_t)b * Tq + t1) * o_rs + h * HDIM;
    #pragma unroll
    for (int nf = 0; nf < 8; nf++) {
        const int col = 8 * nf + 2 * tg;
        *(float2*)&out0[col] = make_float2(o[nf][0] * inv0, o[nf][1] * inv0);
        *(float2*)&out1[col] = make_float2(o[nf][2] * inv1, o[nf][3] * inv1);
    }
}

// ------------------------------- launch --------------------------------------
extern "C" void kernel_launch(void* const* d_in, const int* in_sizes, int n_in,
                              void* d_out, int out_size)
{
    const float* x            = (const float*)d_in[0];
    const float* encoder_x    = (const float*)d_in[1];
    const float* ln1_g        = (const float*)d_in[2];
    const float* ln1_b        = (const float*)d_in[3];
    const float* ln2_g        = (const float*)d_in[4];
    const float* ln2_b        = (const float*)d_in[5];
    const float* ln3_g        = (const float*)d_in[6];
    const float* ln3_b        = (const float*)d_in[7];
    const float* attn_w       = (const float*)d_in[8];
    const float* attn_b       = (const float*)d_in[9];
    const float* attn_proj_w  = (const float*)d_in[10];
    const float* attn_proj_b  = (const float*)d_in[11];
    const float* cross_w      = (const float*)d_in[12];
    const float* cross_b      = (const float*)d_in[13];
    const float* cross_proj_w = (const float*)d_in[14];
    const float* cross_proj_b = (const float*)d_in[15];
    const float* fc_w         = (const float*)d_in[16];
    const float* fc_b         = (const float*)d_in[17];
    const float* proj_w       = (const float*)d_in[18];
    const float* proj_b       = (const float*)d_in[19];

    float *big, *hbuf, *obuf, *xbuf, *q2, *ekv;
    cudaGetSymbolAddress((void**)&big,  g_big);
    cudaGetSymbolAddress((void**)&hbuf, g_h);
    cudaGetSymbolAddress((void**)&obuf, g_o);
    cudaGetSymbolAddress((void**)&xbuf, g_x);
    cudaGetSymbolAddress((void**)&q2,   g_q2);
    cudaGetSymbolAddress((void**)&ekv,  g_ekv);

    cudaFuncSetAttribute(attn_tc_kernel,
                         cudaFuncAttributeMaxDynamicSharedMemorySize,
                         ATTN_SMEM_BYTES);
    cudaFuncSetAttribute(gemm_tf32_kernel,
                         cudaFuncAttributeMaxDynamicSharedMemorySize,
                         GEMM_SMEM_BYTES);

    const int M = MROWS;        // 8192
    dim3 blk(256);
    dim3 ga(TLEN / 128, NHEAD, BATCH);   // 8 x 12 x 8

    // 1. h = LN1(x)
    ln_kernel<<<M, blk>>>(x, ln1_g, ln1_b, hbuf);
    // 2. qkv = h @ attn_w + attn_b   (8192 x 2304)
    gemm_tf32_kernel<<<dim3(2304 / 128, M / 128), blk, GEMM_SMEM_BYTES>>>(
        hbuf, 768, attn_w, 2304, attn_b, nullptr, big, 2304, M, 2304, 768, 0);
    // 3. causal self-attention
    attn_tc_kernel<<<ga, blk, ATTN_SMEM_BYTES>>>(
        big, 2304, big + 768, 2304, big + 1536, 2304, obuf, 768, TLEN, TLEN, 1);
    // 4. x1 = x + o @ attn_proj_w + attn_proj_b
    gemm_tf32_kernel<<<dim3(768 / 128, M / 128), blk, GEMM_SMEM_BYTES>>>(
        obuf, 768, attn_proj_w, 768, attn_proj_b, x, xbuf, 768, M, 768, 768, 1);
    // 5. h = LN2(x1)
    ln_kernel<<<M, blk>>>(xbuf, ln2_g, ln2_b, hbuf);
    // 6. q2 = h @ cross_w[:, :768] + cross_b[:768]
    gemm_tf32_kernel<<<dim3(768 / 128, M / 128), blk, GEMM_SMEM_BYTES>>>(
        hbuf, 768, cross_w, 2304, cross_b, nullptr, q2, 768, M, 768, 768, 0);
    // 7. ekv = encoder_x @ cross_w[:, 768:] + cross_b[768:]   (2056 x 1536)
    gemm_tf32_kernel<<<dim3(1536 / 128, (EROWS + 127) / 128), blk, GEMM_SMEM_BYTES>>>(
        encoder_x, 768, cross_w + 768, 2304, cross_b + 768, nullptr,
        ekv, 1536, EROWS, 1536, 768, 0);
    // 8. cross-attention (non-causal, Tk = 257)
    attn_tc_kernel<<<ga, blk, ATTN_SMEM_BYTES>>>(
        q2, 768, ekv, 1536, ekv + 768, 1536, obuf, 768, TLEN, SLEN, 0);
    // 9. x2 = x1 + o2 @ cross_proj_w + cross_proj_b
    gemm_tf32_kernel<<<dim3(768 / 128, M / 128), blk, GEMM_SMEM_BYTES>>>(
        obuf, 768, cross_proj_w, 768, cross_proj_b, xbuf, xbuf, 768, M, 768, 768, 1);
    // 10. h = LN3(x2)
    ln_kernel<<<M, blk>>>(xbuf, ln3_g, ln3_b, hbuf);
    // 11. fc = GELU(h @ fc_w + fc_b)  (8192 x 3072)
    gemm_tf32_kernel<<<dim3(3072 / 128, M / 128), blk, GEMM_SMEM_BYTES>>>(
        hbuf, 768, fc_w, 3072, fc_b, nullptr, big, 3072, M, 3072, 768, 2);
    // 12. out = x2 + fc @ proj_w + proj_b
    gemm_tf32_kernel<<<dim3(768 / 128, M / 128), blk, GEMM_SMEM_BYTES>>>(
        big, 3072, proj_w, 768, proj_b, xbuf, (float*)d_out, 768, M, 768, 3072, 1);
}